// round 16
// baseline (speedup 1.0000x reference)
#include <cuda_runtime.h>

// KANLayer_60464549593380 on GB300 (sm_103a):
//   out[b] = sum_d P_d(tanh(x[b,d])), P_d = degree-8 monomial poly from
//   w = hweights @ coeffs (summation reorder + Chebyshev->monomial fold).
// R16: occupancy endgame. 1 dim/lane -> 9 scalar coeff regs, ~32 regs total,
// __launch_bounds__(256,8) -> 64 warps/SM (vs 40). Warp = dim octant,
// 16 rows/block, grid 2048. Scalar tanh+Horner (no pack/unpack MOVs),
// LDG.32 1-line/warp, conflict-free STS, shuffle-free.

#define DEG   8
#define NF    9
#define DDIM  256
#define FDIM  2304
#define F4DIM 576
#define ROWS  16            // rows per block
#define PPITCH 257          // part[] pitch in floats

__device__ float g_w[FDIM];

__device__ __forceinline__ float ex2a(float v) {
    float r; asm("ex2.approx.ftz.f32 %0, %1;" : "=f"(r) : "f"(v)); return r;
}
__device__ __forceinline__ float rcpa(float v) {
    float r; asm("rcp.approx.ftz.f32 %0, %1;" : "=f"(r) : "f"(v)); return r;
}
// tanh(v) = (1-e)/(1+e), e = exp(-2v); sign-correct for all v, no overflow.
__device__ __forceinline__ float tanh_fast(float v) {
    float e = ex2a(v * -2.885390081777927f);
    return (1.0f - e) * rcpa(1.0f + e);
}

// ---------------- Prep: w[f] = sum_n hw[n]*coeffs[n,f] ----------------
__global__ void k_wprep(const float4* __restrict__ c4,
                        const float* __restrict__ hw, int N) {
    __shared__ float4 red[128];
    const int col = blockIdx.x;
    const int t   = threadIdx.x;
    float4 s = make_float4(0.f, 0.f, 0.f, 0.f);
    for (int n = t; n < N; n += 128) {
        float  h = hw[n];
        float4 v = c4[(size_t)n * F4DIM + col];
        s.x = fmaf(h, v.x, s.x);
        s.y = fmaf(h, v.y, s.y);
        s.z = fmaf(h, v.z, s.z);
        s.w = fmaf(h, v.w, s.w);
    }
    red[t] = s;
    __syncthreads();
    #pragma unroll
    for (int o = 64; o >= 1; o >>= 1) {
        if (t < o) {
            float4 b = red[t + o];
            red[t].x += b.x; red[t].y += b.y; red[t].z += b.z; red[t].w += b.w;
        }
        __syncthreads();
    }
    if (t == 0) ((float4*)g_w)[col] = red[0];
}

// Chebyshev -> monomial for one dim's 9 weights.
__device__ __forceinline__ void cheb2mono(const float* __restrict__ w, float* a) {
    a[0] = w[0] - w[2] + w[4] - w[6] + w[8];
    a[1] = w[1] - 3.f * w[3] + 5.f * w[5] - 7.f * w[7];
    a[2] = 2.f * w[2] - 8.f * w[4] + 18.f * w[6] - 32.f * w[8];
    a[3] = 4.f * w[3] - 20.f * w[5] + 56.f * w[7];
    a[4] = 8.f * w[4] - 48.f * w[6] + 160.f * w[8];
    a[5] = 16.f * w[5] - 112.f * w[7];
    a[6] = 32.f * w[6] - 256.f * w[8];
    a[7] = 64.f * w[7];
    a[8] = 128.f * w[8];
}

// ---------------- Main ----------------
// 256 threads = 8 warps, 16 rows/block, grid 2048.
// Warp w owns dim octant [32w, 32w+32); lane owns ONE dim d0 = 32w + lane.
// Iter i (row row0+i): lane reads x[row][d0] (warp: 128B = 1 line),
// scalar tanh + 8-FMA Horner, STS part[i][d0] (consecutive -> conflict-free).
// No shuffles, no loop barriers, ~32 regs -> 8 blocks/SM (full 64 warps).
__global__ void __launch_bounds__(256, 8)
k_main(const float* __restrict__ x, float* __restrict__ out, int B) {
    __shared__ float part[ROWS][PPITCH];          // 16.4 KB
    __shared__ float red2[ROWS][17];              // 1.1 KB
    const int t    = threadIdx.x;
    const int lane = t & 31;
    const int w    = t >> 5;
    const int d0   = 32 * w + lane;
    const size_t row0 = (size_t)blockIdx.x * ROWS;

    // Monomial coefficients for this lane's single dim.
    float a[NF];
    {
        float wb[NF];
        #pragma unroll
        for (int k = 0; k < NF; ++k) wb[k] = g_w[d0 * NF + k];
        cheb2mono(wb, a);
    }

    const float* xp = x + row0 * DDIM + d0;

    #pragma unroll
    for (int i = 0; i < ROWS; ++i) {
        float xv = xp[i * DDIM];
        float tv = tanh_fast(xv);
        float h  = a[DEG];
        #pragma unroll
        for (int j = DEG - 1; j >= 0; --j)
            h = fmaf(tv, h, a[j]);
        part[i][d0] = h;
    }

    __syncthreads();
    // Tail step 1: 256 threads; thread (r, seg) sums 16 of row r's 256 partials.
    {
        const int r = t >> 4, seg = t & 15;
        const float* pr = part[r] + 16 * seg;
        float s0 = 0.f, s1 = 0.f;
        #pragma unroll
        for (int k = 0; k < 16; k += 2) { s0 += pr[k]; s1 += pr[k + 1]; }
        red2[r][seg] = s0 + s1;
    }
    __syncthreads();
    // Step 2: 16 threads; each sums its row's 16 sub-partials.
    if (t < ROWS) {
        const float* rr = red2[t];
        float s = 0.f;
        #pragma unroll
        for (int k = 0; k < 16; ++k) s += rr[k];
        size_t row = row0 + t;
        if (row < (size_t)B) out[row] = s;
    }
}

extern "C" void kernel_launch(void* const* d_in, const int* in_sizes, int n_in,
                              void* d_out, int out_size) {
    const float* x      = (const float*)d_in[0];
    const float* coeffs = (const float*)d_in[1];
    const float* hw     = (const float*)d_in[2];
    float* out = (float*)d_out;

    const int B = out_size;       // 32768 = 2048 * 16
    const int N = in_sizes[2];    // 256

    k_wprep<<<F4DIM, 128>>>((const float4*)coeffs, hw, N);
    k_main<<<(B + ROWS - 1) / ROWS, 256>>>(x, out, B);
}

// round 17
// speedup vs baseline: 1.4076x; 1.4076x over previous
#include <cuda_runtime.h>

// KANLayer_60464549593380 on GB300 (sm_103a):
//   out[b] = sum_d P_d(tanh(x[b,d])), P_d = degree-8 monomial poly from
//   w = hweights @ coeffs (summation reorder + Chebyshev->monomial fold).
// R17 = R13 (best, 15.1us) minus removable instructions:
//   - x loaded as u64 (no pack MOVs)
//   - partial kept packed, STS.64 (no unpack_sum in loop)
//   - launch_bounds(256,6) -> <=40 regs, 6 blocks/SM
// Model: wall == sum of per-SMSP pipe demands (issue+MUFU+fma+LSU); cut issue.

#define DEG   8
#define NF    9
#define DDIM  256
#define FDIM  2304
#define F4DIM 576
#define ROWS  32            // rows per block
#define PP2   129           // part2[] pitch in u64

__device__ float g_w[FDIM];

typedef unsigned long long u64;

// ---------------- packed f32x2 / MUFU helpers ----------------
__device__ __forceinline__ u64 fma2(u64 a, u64 b, u64 c) {
    u64 d; asm("fma.rn.f32x2 %0, %1, %2, %3;" : "=l"(d) : "l"(a), "l"(b), "l"(c));
    return d;
}
__device__ __forceinline__ u64 add2(u64 a, u64 b) {
    u64 d; asm("add.rn.f32x2 %0, %1, %2;" : "=l"(d) : "l"(a), "l"(b));
    return d;
}
__device__ __forceinline__ u64 mul2(u64 a, u64 b) {
    u64 d; asm("mul.rn.f32x2 %0, %1, %2;" : "=l"(d) : "l"(a), "l"(b));
    return d;
}
__device__ __forceinline__ u64 pack2(float lo, float hi) {
    u64 d; asm("mov.b64 %0, {%1, %2};" : "=l"(d) : "f"(lo), "f"(hi));
    return d;
}
__device__ __forceinline__ float ex2a(float v) {
    float r; asm("ex2.approx.ftz.f32 %0, %1;" : "=f"(r) : "f"(v)); return r;
}
__device__ __forceinline__ float rcpa(float v) {
    float r; asm("rcp.approx.ftz.f32 %0, %1;" : "=f"(r) : "f"(v)); return r;
}

// Packed tanh of 2 values: t = (1-e)/(1+e), e = exp(-2v).
__device__ __forceinline__ u64 tanh2(u64 v2) {
    const u64 ONE2  = 0x3f8000003f800000ull;   // (1.0f, 1.0f)
    const u64 NEG12 = 0xbf800000bf800000ull;   // (-1.0f, -1.0f)
    const u64 SC2   = 0xc038aa3bc038aa3bull;   // (-2*log2e) x2
    u64 s2 = mul2(v2, SC2);
    float slo, shi;
    asm("mov.b64 {%0, %1}, %2;" : "=f"(slo), "=f"(shi) : "l"(s2));
    u64 e2 = pack2(ex2a(slo), ex2a(shi));
    u64 num = fma2(e2, NEG12, ONE2);           // 1 - e
    u64 den = add2(e2, ONE2);                  // 1 + e
    float dlo, dhi;
    asm("mov.b64 {%0, %1}, %2;" : "=f"(dlo), "=f"(dhi) : "l"(den));
    u64 r2 = pack2(rcpa(dlo), rcpa(dhi));
    return mul2(num, r2);
}

// ---------------- Prep: w[f] = sum_n hw[n]*coeffs[n,f] ----------------
__global__ void k_wprep(const float4* __restrict__ c4,
                        const float* __restrict__ hw, int N) {
    __shared__ float4 red[128];
    const int col = blockIdx.x;
    const int t   = threadIdx.x;
    float4 s = make_float4(0.f, 0.f, 0.f, 0.f);
    for (int n = t; n < N; n += 128) {
        float  h = hw[n];
        float4 v = c4[(size_t)n * F4DIM + col];
        s.x = fmaf(h, v.x, s.x);
        s.y = fmaf(h, v.y, s.y);
        s.z = fmaf(h, v.z, s.z);
        s.w = fmaf(h, v.w, s.w);
    }
    red[t] = s;
    __syncthreads();
    #pragma unroll
    for (int o = 64; o >= 1; o >>= 1) {
        if (t < o) {
            float4 b = red[t + o];
            red[t].x += b.x; red[t].y += b.y; red[t].z += b.z; red[t].w += b.w;
        }
        __syncthreads();
    }
    if (t == 0) ((float4*)g_w)[col] = red[0];
}

// Chebyshev -> monomial for one dim's 9 weights.
__device__ __forceinline__ void cheb2mono(const float* __restrict__ w, float* a) {
    a[0] = w[0] - w[2] + w[4] - w[6] + w[8];
    a[1] = w[1] - 3.f * w[3] + 5.f * w[5] - 7.f * w[7];
    a[2] = 2.f * w[2] - 8.f * w[4] + 18.f * w[6] - 32.f * w[8];
    a[3] = 4.f * w[3] - 20.f * w[5] + 56.f * w[7];
    a[4] = 8.f * w[4] - 48.f * w[6] + 160.f * w[8];
    a[5] = 16.f * w[5] - 112.f * w[7];
    a[6] = 32.f * w[6] - 256.f * w[8];
    a[7] = 64.f * w[7];
    a[8] = 128.f * w[8];
}

// ---------------- Main ----------------
// 256 threads = 8 warps, 32 rows/block, grid 1024 (8192 warps).
// Warp w: quarter q = w&3 (dims 64q..64q+63), row group g = w>>2
// (rows 16g..16g+15). Lane owns 2 fixed dims: d0 = 64q + 2*lane.
// Iter i: row 16g+i; lane loads x-pair as u64 (warp: 256B contiguous),
// packed tanh + packed Horner, STS.64 packed partial. No shuffles/barriers.
__global__ void __launch_bounds__(256, 6)
k_main(const float* __restrict__ x, float* __restrict__ out, int B) {
    __shared__ u64 part2[ROWS][PP2];              // 33 KB (row-major u64)
    __shared__ u64 red2[ROWS][9];                 // 2.3 KB
    const int t    = threadIdx.x;
    const int lane = t & 31;
    const int w    = t >> 5;
    const int q    = w & 3;
    const int g    = w >> 2;
    const size_t row0 = (size_t)blockIdx.x * ROWS;

    // Coefficients for this lane's 2 dims, packed as one chain.
    u64 c[NF];
    {
        const int d0 = 64 * q + 2 * lane;
        const float2* wp = (const float2*)(g_w + d0 * NF);  // 18 floats, 8B-aligned
        float wb[2 * NF];
        #pragma unroll
        for (int k = 0; k < NF; ++k) ((float2*)wb)[k] = wp[k];
        float alo[NF], ahi[NF];
        cheb2mono(wb, alo);
        cheb2mono(wb + NF, ahi);
        #pragma unroll
        for (int j = 0; j < NF; ++j) c[j] = pack2(alo[j], ahi[j]);
    }

    // u64 (float-pair) index for row r: (row0 + 16g + r)*128 + 32q + lane.
    const u64* xp = (const u64*)x + (row0 + 16 * g) * 128 + 32 * q + lane;

    u64 xv = xp[0];
    #pragma unroll
    for (int i = 0; i < 16; ++i) {
        u64 xn;
        if (i < 15) xn = xp[(size_t)(i + 1) * 128];

        u64 tp = tanh2(xv);
        u64 h  = c[DEG];
        #pragma unroll
        for (int j = DEG - 1; j >= 0; --j)
            h = fma2(tp, h, c[j]);
        part2[16 * g + i][32 * q + lane] = h;     // STS.64, unique slot per warp

        xv = xn;
    }

    __syncthreads();
    // Tail step 1: 256 threads; thread (r = t&31, seg = t>>5) sums 16
    // consecutive u64-partials of row r. Lane=row -> 2-way bank conflicts max.
    {
        const int r = t & 31, seg = t >> 5;       // seg 0..7
        const u64* pr = part2[r] + 16 * seg;
        float sx = 0.f, sy = 0.f;
        #pragma unroll
        for (int k = 0; k < 16; ++k) {
            float2 v = *(const float2*)&pr[k];
            sx += v.x; sy += v.y;
        }
        float2 o; o.x = sx; o.y = sy;
        red2[r][seg] = *(const u64*)&o;
    }
    __syncthreads();
    // Step 2: 32 threads; each sums its row's 8 sub-partials.
    if (t < ROWS) {
        const u64* rr = red2[t];
        float s = 0.f;
        #pragma unroll
        for (int k = 0; k < 8; ++k) {
            float2 v = *(const float2*)&rr[k];
            s += v.x + v.y;
        }
        size_t row = row0 + t;
        if (row < (size_t)B) out[row] = s;
    }
}

extern "C" void kernel_launch(void* const* d_in, const int* in_sizes, int n_in,
                              void* d_out, int out_size) {
    const float* x      = (const float*)d_in[0];
    const float* coeffs = (const float*)d_in[1];
    const float* hw     = (const float*)d_in[2];
    float* out = (float*)d_out;

    const int B = out_size;       // 32768 = 1024 * 32
    const int N = in_sizes[2];    // 256

    k_wprep<<<F4DIM, 128>>>((const float4*)coeffs, hw, N);
    k_main<<<(B + ROWS - 1) / ROWS, 256>>>(x, out, B);
}